// round 3
// baseline (speedup 1.0000x reference)
#include <cuda_runtime.h>

#define NN 100000
#define NE 3200000

typedef unsigned long long ull;

// ---------------- device scratch ----------------
__device__ int2   g_edges[NE];      // (src, norm-as-float-bits), CSR by dst
__device__ int    g_src[NE];
__device__ int    g_dst[NE];
__device__ int    g_cnt[NN];
__device__ int    g_rowptr[NN + 1];
__device__ int    g_cursor[NN];
__device__ int    g_bsum[128];
__device__ int    g_bsumEx[128];
__device__ float  g_dinv[NN];
__device__ float4 g_bufA[NN * 4];   // xw  -> (reused) H
__device__ float4 g_bufC[NN * 4];   // xw2
__device__ float4 g_x1[NN * 4];
__device__ float4 g_x2[NN * 4];

// ---------------- helpers ----------------
__device__ __forceinline__ float sigm_f(float x) {
    return __fdividef(1.0f, 1.0f + __expf(-x));
}
__device__ __forceinline__ float tanh_f(float x) {
    float e = __expf(2.0f * x);
    return 1.0f - __fdividef(2.0f, e + 1.0f);
}
__device__ __forceinline__ void fma4(float* a, float w, float4 v) {
    a[0] += w * v.x; a[1] += w * v.y; a[2] += w * v.z; a[3] += w * v.w;
}
__device__ __forceinline__ ull pack2(float a, float b) {
    ull r;
    asm("mov.b64 %0, {%1, %2};" : "=l"(r) : "f"(a), "f"(b));
    return r;
}
__device__ __forceinline__ ull fma2(ull a, ull b, ull c) {
    ull d;
    asm("fma.rn.f32x2 %0, %1, %2, %3;" : "=l"(d) : "l"(a), "l"(b), "l"(c));
    return d;
}
__device__ __forceinline__ void unpack2(ull v, float& a, float& b) {
    asm("mov.b64 {%0, %1}, %2;" : "=f"(a), "=f"(b) : "l"(v));
}

// ---------------- graph preprocessing ----------------
__global__ void k_zero() {
    int i = blockIdx.x * blockDim.x + threadIdx.x;
    if (i < NN) g_cnt[i] = 0;
}

__global__ void k_count(const int* __restrict__ ei, int is64) {
    int e = blockIdx.x * blockDim.x + threadIdx.x;
    if (e >= NE) return;
    int s, d;
    if (is64) {
        s = ei[2 * e];
        d = ei[2 * (NE + e)];
    } else {
        s = ei[e];
        d = ei[NE + e];
    }
    g_src[e] = s; g_dst[e] = d;
    atomicAdd(&g_cnt[d], 1);
}

__global__ void k_dinv() {
    int i = blockIdx.x * blockDim.x + threadIdx.x;
    if (i < NN) g_dinv[i] = rsqrtf((float)g_cnt[i] + 1.0f);
}

__global__ void k_scanA() {
    __shared__ int sh[1024];
    int i = blockIdx.x * 1024 + threadIdx.x;
    int v = (i < NN) ? g_cnt[i] : 0;
    sh[threadIdx.x] = v;
    __syncthreads();
    #pragma unroll
    for (int off = 1; off < 1024; off <<= 1) {
        int t = (threadIdx.x >= off) ? sh[threadIdx.x - off] : 0;
        __syncthreads();
        sh[threadIdx.x] += t;
        __syncthreads();
    }
    if (i < NN) g_rowptr[i] = sh[threadIdx.x] - v;
    if (threadIdx.x == 1023) g_bsum[blockIdx.x] = sh[1023];
}

__global__ void k_scanB(int nb) {
    __shared__ int sh[128];
    int t = threadIdx.x;
    int v = (t < nb) ? g_bsum[t] : 0;
    sh[t] = v;
    __syncthreads();
    #pragma unroll
    for (int off = 1; off < 128; off <<= 1) {
        int tv = (t >= off) ? sh[t - off] : 0;
        __syncthreads();
        sh[t] += tv;
        __syncthreads();
    }
    g_bsumEx[t] = sh[t] - v;
}

__global__ void k_scanC() {
    int i = blockIdx.x * blockDim.x + threadIdx.x;
    if (i < NN) {
        int r = g_rowptr[i] + g_bsumEx[i >> 10];
        g_rowptr[i] = r;
        g_cursor[i] = r;
    }
    if (i == 0) g_rowptr[NN] = NE;
}

__global__ void k_scatter() {
    int e = blockIdx.x * blockDim.x + threadIdx.x;
    if (e >= NE) return;
    int s = g_src[e], d = g_dst[e];
    int p = atomicAdd(&g_cursor[d], 1);
    g_edges[p] = make_int2(s, __float_as_int(g_dinv[s] * g_dinv[d]));
}

// ---------------- GEMM1: xw = x[100000,512] @ W1[512,16] (f32x2 packed) --------
__global__ void __launch_bounds__(256) k_gemm1(const float4* __restrict__ x4,
                                               const float* __restrict__ w) {
    __shared__ float xs[256][33];
    __shared__ ulonglong2 sw[128];   // 32 rows x 16 floats as 4 ull2/row
    int tid = threadIdx.x;
    int row = blockIdx.x * 256 + tid;
    ull acc2[8];
    #pragma unroll
    for (int p = 0; p < 8; p++) acc2[p] = 0ULL;

    const ulonglong2* w16 = (const ulonglong2*)w;

    for (int kc = 0; kc < 16; kc++) {
        #pragma unroll
        for (int j = 0; j < 8; j++) {
            int idx = j * 256 + tid;
            int r = idx >> 3, c4 = idx & 7;
            int gr = blockIdx.x * 256 + r;
            float4 v = (gr < NN) ? x4[gr * 128 + kc * 8 + c4]
                                 : make_float4(0.f, 0.f, 0.f, 0.f);
            xs[r][c4 * 4 + 0] = v.x; xs[r][c4 * 4 + 1] = v.y;
            xs[r][c4 * 4 + 2] = v.z; xs[r][c4 * 4 + 3] = v.w;
        }
        if (tid < 128) sw[tid] = w16[kc * 128 + tid];
        __syncthreads();
        #pragma unroll
        for (int k = 0; k < 32; k++) {
            float xv = xs[tid][k];
            ull xd = pack2(xv, xv);
            ulonglong2 w0 = sw[k * 4 + 0], w1 = sw[k * 4 + 1];
            ulonglong2 w2v = sw[k * 4 + 2], w3v = sw[k * 4 + 3];
            acc2[0] = fma2(w0.x,  xd, acc2[0]);
            acc2[1] = fma2(w0.y,  xd, acc2[1]);
            acc2[2] = fma2(w1.x,  xd, acc2[2]);
            acc2[3] = fma2(w1.y,  xd, acc2[3]);
            acc2[4] = fma2(w2v.x, xd, acc2[4]);
            acc2[5] = fma2(w2v.y, xd, acc2[5]);
            acc2[6] = fma2(w3v.x, xd, acc2[6]);
            acc2[7] = fma2(w3v.y, xd, acc2[7]);
        }
        __syncthreads();
    }
    if (row < NN) {
        float o[16];
        #pragma unroll
        for (int p = 0; p < 8; p++) unpack2(acc2[p], o[2 * p], o[2 * p + 1]);
        g_bufA[row * 4 + 0] = make_float4(o[0],  o[1],  o[2],  o[3]);
        g_bufA[row * 4 + 1] = make_float4(o[4],  o[5],  o[6],  o[7]);
        g_bufA[row * 4 + 2] = make_float4(o[8],  o[9],  o[10], o[11]);
        g_bufA[row * 4 + 3] = make_float4(o[12], o[13], o[14], o[15]);
    }
}

// ---------------- GCN aggregation: warp-per-node, 4 lanes per edge --------------
// MODE 0: in=g_bufA -> x1 = relu(agg+b1) -> g_x1 ; y = x1@W2 -> g_bufC
// MODE 1: in=g_bufC -> x2 = relu(agg+b2) -> g_x2
// MODE 2: in=g_bufA -> logits = agg@lin_w + lin_b -> log_softmax -> outp
template <int MODE>
__global__ void __launch_bounds__(256) k_agg(float* __restrict__ outp,
                                             const float* __restrict__ bias,
                                             const float4* __restrict__ W4,
                                             const float* __restrict__ Wb) {
    __shared__ float4 sW[160];
    __shared__ float  sx[8][16];
    if (MODE == 0) { if (threadIdx.x < 64)  sW[threadIdx.x] = W4[threadIdx.x]; }
    if (MODE == 2) { if (threadIdx.x < 160) sW[threadIdx.x] = W4[threadIdx.x]; }
    __syncthreads();

    int warp = threadIdx.x >> 5;
    int lane = threadIdx.x & 31;
    int g = lane >> 2, q = lane & 3;
    int n = blockIdx.x * 8 + warp;
    if (n >= NN) return;

    const float4* in4 = (MODE == 1) ? g_bufC : g_bufA;

    float4 acc = make_float4(0.f, 0.f, 0.f, 0.f);
    if (g == 0) {
        float dd = g_dinv[n]; dd *= dd;
        float4 a = in4[n * 4 + q];
        acc.x = dd * a.x; acc.y = dd * a.y; acc.z = dd * a.z; acc.w = dd * a.w;
    }

    int beg = g_rowptr[n], end = g_rowptr[n + 1];
    for (int e = beg + g; e < end; e += 8) {
        int2 ev = g_edges[e];
        float w = __int_as_float(ev.y);
        float4 v = in4[ev.x * 4 + q];
        acc.x += w * v.x; acc.y += w * v.y; acc.z += w * v.z; acc.w += w * v.w;
    }

    // reduce over the 8 edge-groups (lanes with same q)
    #pragma unroll
    for (int off = 4; off < 32; off <<= 1) {
        acc.x += __shfl_xor_sync(0xffffffffu, acc.x, off);
        acc.y += __shfl_xor_sync(0xffffffffu, acc.y, off);
        acc.z += __shfl_xor_sync(0xffffffffu, acc.z, off);
        acc.w += __shfl_xor_sync(0xffffffffu, acc.w, off);
    }

    if (MODE == 0 || MODE == 1) {
        if (g == 0) {
            float4 b = ((const float4*)bias)[q];
            float4 xr;
            xr.x = fmaxf(acc.x + b.x, 0.0f);
            xr.y = fmaxf(acc.y + b.y, 0.0f);
            xr.z = fmaxf(acc.z + b.z, 0.0f);
            xr.w = fmaxf(acc.w + b.w, 0.0f);
            float4* ox = (MODE == 0) ? (g_x1 + n * 4) : (g_x2 + n * 4);
            ox[q] = xr;
            if (MODE == 0) {
                sx[warp][q * 4 + 0] = xr.x; sx[warp][q * 4 + 1] = xr.y;
                sx[warp][q * 4 + 2] = xr.z; sx[warp][q * 4 + 3] = xr.w;
            }
        }
        if (MODE == 0) {
            __syncwarp();
            if (g == 0) {
                float y[4] = {0.f, 0.f, 0.f, 0.f};
                #pragma unroll
                for (int k = 0; k < 16; k++) {
                    float xv = sx[warp][k];
                    float4 w = sW[k * 4 + q];
                    y[0] += xv * w.x; y[1] += xv * w.y;
                    y[2] += xv * w.z; y[3] += xv * w.w;
                }
                g_bufC[n * 4 + q] = make_float4(y[0], y[1], y[2], y[3]);
            }
        }
    } else {  // MODE 2
        if (g == 0) {
            sx[warp][q * 4 + 0] = acc.x; sx[warp][q * 4 + 1] = acc.y;
            sx[warp][q * 4 + 2] = acc.z; sx[warp][q * 4 + 3] = acc.w;
        }
        __syncwarp();
        const float* sWf = (const float*)sW;
        float v0 = __ldg(&Wb[lane]);
        float v1 = (lane < 8) ? __ldg(&Wb[32 + lane]) : -1e30f;
        #pragma unroll
        for (int k = 0; k < 16; k++) {
            float a = sx[warp][k];
            v0 += a * sWf[k * 40 + lane];
            if (lane < 8) v1 += a * sWf[k * 40 + 32 + lane];
        }
        float m = fmaxf(v0, v1);
        #pragma unroll
        for (int off = 1; off < 32; off <<= 1)
            m = fmaxf(m, __shfl_xor_sync(0xffffffffu, m, off));
        float s = __expf(v0 - m) + ((lane < 8) ? __expf(v1 - m) : 0.0f);
        #pragma unroll
        for (int off = 1; off < 32; off <<= 1)
            s += __shfl_xor_sync(0xffffffffu, s, off);
        float lse = m + __logf(s);
        outp[n * 40 + lane] = v0 - lse;
        if (lane < 8) outp[n * 40 + 32 + lane] = v1 - lse;
    }
}

// ---------------- JK bidirectional LSTM + attention (f32x2 packed) --------------
// dynamic shared layout (bytes):
//   0     : ihf float4[512]   (gate,jp,kk) -> (w[2jp][2kk], w[2jp+1][2kk], w[2jp][2kk+1], w[2jp+1][2kk+1])
//   8192  : ihb float4[512]
//   16384 : hhf float4[1024]
//   32768 : hhb float4[1024]
//   49152 : bf2 float2[64]    (gate*16+jp) -> (b[g*32+2jp], b[g*32+2jp+1])
//   49664 : bb2 float2[64]
//   50176 : aw  float[64]
#define SMEM_LSTM 50432

__device__ __forceinline__ void load16(const float4* p, float* x) {
    #pragma unroll
    for (int q = 0; q < 4; q++) {
        float4 t = p[q];
        x[q * 4 + 0] = t.x; x[q * 4 + 1] = t.y; x[q * 4 + 2] = t.z; x[q * 4 + 3] = t.w;
    }
}

// cell with zero initial state: gates i,g,o; writes h,c; accumulates score
__device__ __forceinline__ void cell0(const float* x, float* h, float* c,
                                      const float4* sih, const float2* sb,
                                      const float* sawh, float& s) {
    #pragma unroll
    for (int jp = 0; jp < 16; jp++) {
        ull ai = *(const ull*)&sb[jp];
        ull ag = *(const ull*)&sb[32 + jp];
        ull ao = *(const ull*)&sb[48 + jp];
        #pragma unroll
        for (int kk = 0; kk < 8; kk++) {
            ull xlo = pack2(x[2 * kk], x[2 * kk]);
            ull xhi = pack2(x[2 * kk + 1], x[2 * kk + 1]);
            ulonglong2 wi = *(const ulonglong2*)&sih[(0 * 16 + jp) * 8 + kk];
            ulonglong2 wg = *(const ulonglong2*)&sih[(2 * 16 + jp) * 8 + kk];
            ulonglong2 wo = *(const ulonglong2*)&sih[(3 * 16 + jp) * 8 + kk];
            ai = fma2(wi.x, xlo, ai); ai = fma2(wi.y, xhi, ai);
            ag = fma2(wg.x, xlo, ag); ag = fma2(wg.y, xhi, ag);
            ao = fma2(wo.x, xlo, ao); ao = fma2(wo.y, xhi, ao);
        }
        float i0, i1, g0, g1, o0, o1;
        unpack2(ai, i0, i1); unpack2(ag, g0, g1); unpack2(ao, o0, o1);
        float c0 = sigm_f(i0) * tanh_f(g0), c1 = sigm_f(i1) * tanh_f(g1);
        c[2 * jp] = c0; c[2 * jp + 1] = c1;
        float h0 = sigm_f(o0) * tanh_f(c0), h1 = sigm_f(o1) * tanh_f(c1);
        h[2 * jp] = h0; h[2 * jp + 1] = h1;
        s += h0 * sawh[2 * jp] + h1 * sawh[2 * jp + 1];
    }
}

// full cell: consumes existing h,c (read-only); accumulates score of new h
__device__ __forceinline__ void cell1(const float* x, const float* h, const float* c,
                                      const float4* sih, const float4* shh,
                                      const float2* sb, const float* sawh, float& s) {
    #pragma unroll
    for (int jp = 0; jp < 16; jp++) {
        ull ai = *(const ull*)&sb[jp];
        ull af = *(const ull*)&sb[16 + jp];
        ull ag = *(const ull*)&sb[32 + jp];
        ull ao = *(const ull*)&sb[48 + jp];
        #pragma unroll
        for (int kk = 0; kk < 8; kk++) {
            ull xlo = pack2(x[2 * kk], x[2 * kk]);
            ull xhi = pack2(x[2 * kk + 1], x[2 * kk + 1]);
            ulonglong2 wi = *(const ulonglong2*)&sih[(0 * 16 + jp) * 8 + kk];
            ulonglong2 wf = *(const ulonglong2*)&sih[(1 * 16 + jp) * 8 + kk];
            ulonglong2 wg = *(const ulonglong2*)&sih[(2 * 16 + jp) * 8 + kk];
            ulonglong2 wo = *(const ulonglong2*)&sih[(3 * 16 + jp) * 8 + kk];
            ai = fma2(wi.x, xlo, ai); ai = fma2(wi.y, xhi, ai);
            af = fma2(wf.x, xlo, af); af = fma2(wf.y, xhi, af);
            ag = fma2(wg.x, xlo, ag); ag = fma2(wg.y, xhi, ag);
            ao = fma2(wo.x, xlo, ao); ao = fma2(wo.y, xhi, ao);
        }
        #pragma unroll
        for (int kk = 0; kk < 16; kk++) {
            ull hlo = pack2(h[2 * kk], h[2 * kk]);
            ull hhi = pack2(h[2 * kk + 1], h[2 * kk + 1]);
            ulonglong2 wi = *(const ulonglong2*)&shh[(0 * 16 + jp) * 16 + kk];
            ulonglong2 wf = *(const ulonglong2*)&shh[(1 * 16 + jp) * 16 + kk];
            ulonglong2 wg = *(const ulonglong2*)&shh[(2 * 16 + jp) * 16 + kk];
            ulonglong2 wo = *(const ulonglong2*)&shh[(3 * 16 + jp) * 16 + kk];
            ai = fma2(wi.x, hlo, ai); ai = fma2(wi.y, hhi, ai);
            af = fma2(wf.x, hlo, af); af = fma2(wf.y, hhi, af);
            ag = fma2(wg.x, hlo, ag); ag = fma2(wg.y, hhi, ag);
            ao = fma2(wo.x, hlo, ao); ao = fma2(wo.y, hhi, ao);
        }
        float i0, i1, f0, f1, g0, g1, o0, o1;
        unpack2(ai, i0, i1); unpack2(af, f0, f1);
        unpack2(ag, g0, g1); unpack2(ao, o0, o1);
        float c0 = sigm_f(f0) * c[2 * jp]     + sigm_f(i0) * tanh_f(g0);
        float c1 = sigm_f(f1) * c[2 * jp + 1] + sigm_f(i1) * tanh_f(g1);
        float h0 = sigm_f(o0) * tanh_f(c0), h1 = sigm_f(o1) * tanh_f(c1);
        s += h0 * sawh[2 * jp] + h1 * sawh[2 * jp + 1];
    }
}

__global__ void __launch_bounds__(128) k_lstm(
    const float* __restrict__ wihf, const float* __restrict__ whhf, const float* __restrict__ bf,
    const float* __restrict__ wihb, const float* __restrict__ whhb, const float* __restrict__ bb,
    const float* __restrict__ aw, const float* __restrict__ ab) {
    extern __shared__ char sm[];
    float4* sihf = (float4*)(sm);
    float4* sihb = (float4*)(sm + 8192);
    float4* shhf = (float4*)(sm + 16384);
    float4* shhb = (float4*)(sm + 32768);
    float2* sbf  = (float2*)(sm + 49152);
    float2* sbb  = (float2*)(sm + 49664);
    float*  saw  = (float*)(sm + 50176);

    int tid = threadIdx.x;
    for (int i = tid; i < 512; i += 128) {
        int kk = i & 7, jp = (i >> 3) & 15, gg = i >> 7;
        int r = gg * 32 + 2 * jp, k = 2 * kk;
        sihf[i] = make_float4(wihf[r * 16 + k], wihf[(r + 1) * 16 + k],
                              wihf[r * 16 + k + 1], wihf[(r + 1) * 16 + k + 1]);
        sihb[i] = make_float4(wihb[r * 16 + k], wihb[(r + 1) * 16 + k],
                              wihb[r * 16 + k + 1], wihb[(r + 1) * 16 + k + 1]);
    }
    for (int i = tid; i < 1024; i += 128) {
        int kk = i & 15, jp = (i >> 4) & 15, gg = i >> 8;
        int r = gg * 32 + 2 * jp, k = 2 * kk;
        shhf[i] = make_float4(whhf[r * 32 + k], whhf[(r + 1) * 32 + k],
                              whhf[r * 32 + k + 1], whhf[(r + 1) * 32 + k + 1]);
        shhb[i] = make_float4(whhb[r * 32 + k], whhb[(r + 1) * 32 + k],
                              whhb[r * 32 + k + 1], whhb[(r + 1) * 32 + k + 1]);
    }
    if (tid < 64) {
        int gg = tid >> 4, jp = tid & 15;
        sbf[tid] = make_float2(bf[gg * 32 + 2 * jp], bf[gg * 32 + 2 * jp + 1]);
        sbb[tid] = make_float2(bb[gg * 32 + 2 * jp], bb[gg * 32 + 2 * jp + 1]);
        saw[tid] = aw[tid];
    }
    __syncthreads();

    int n = blockIdx.x * 128 + tid;
    if (n >= NN) return;

    float xa[16], xb[16];
    load16(g_x1 + n * 4, xa);
    load16(g_x2 + n * 4, xb);

    float h[32], c[32];
    float s0 = 0.0f, s1 = 0.0f;

    cell0(xa, h, c, sihf, sbf, saw,      s0);   // fwd t=0
    cell1(xb, h, c, sihf, shhf, sbf, saw, s1);  // fwd t=1
    cell0(xb, h, c, sihb, sbb, saw + 32, s1);   // bwd t=1
    cell1(xa, h, c, sihb, shhb, sbb, saw + 32, s0);  // bwd t=0

    float abv = __ldg(ab);
    s0 += abv; s1 += abv;
    float m = fmaxf(s0, s1);
    float e0 = __expf(s0 - m), e1 = __expf(s1 - m);
    float inv = __fdividef(1.0f, e0 + e1);
    float a0 = e0 * inv, a1 = e1 * inv;
    #pragma unroll
    for (int q = 0; q < 4; q++) {
        float4 o;
        o.x = a0 * xa[q * 4 + 0] + a1 * xb[q * 4 + 0];
        o.y = a0 * xa[q * 4 + 1] + a1 * xb[q * 4 + 1];
        o.z = a0 * xa[q * 4 + 2] + a1 * xb[q * 4 + 2];
        o.w = a0 * xa[q * 4 + 3] + a1 * xb[q * 4 + 3];
        g_bufA[n * 4 + q] = o;
    }
}

// ---------------- launch ----------------
extern "C" void kernel_launch(void* const* d_in, const int* in_sizes, int n_in,
                              void* d_out, int out_size) {
    int is64 = (in_sizes[1] >= 4 * NE) ? 1 : 0;

    const int NB_N  = (NN + 255) / 256;
    const int NB_E  = (NE + 255) / 256;
    const int NB_SC = (NN + 1023) / 1024;
    const int NB_W  = (NN + 7) / 8;       // warp-per-node agg blocks

    cudaFuncSetAttribute(k_lstm, cudaFuncAttributeMaxDynamicSharedMemorySize, SMEM_LSTM);

    k_zero<<<NB_N, 256>>>();
    k_count<<<NB_E, 256>>>((const int*)d_in[1], is64);
    k_dinv<<<NB_N, 256>>>();
    k_scanA<<<NB_SC, 1024>>>();
    k_scanB<<<1, 128>>>(NB_SC);
    k_scanC<<<NB_N, 256>>>();
    k_scatter<<<NB_E, 256>>>();

    k_gemm1<<<NB_N, 256>>>((const float4*)d_in[0], (const float*)d_in[2]);

    k_agg<0><<<NB_W, 256>>>(nullptr, (const float*)d_in[3], (const float4*)d_in[4], nullptr);
    k_agg<1><<<NB_W, 256>>>(nullptr, (const float*)d_in[5], nullptr, nullptr);

    k_lstm<<<(NN + 127) / 128, 128, SMEM_LSTM>>>(
        (const float*)d_in[6], (const float*)d_in[7], (const float*)d_in[8],
        (const float*)d_in[9], (const float*)d_in[10], (const float*)d_in[11],
        (const float*)d_in[12], (const float*)d_in[13]);

    k_agg<2><<<NB_W, 256>>>((float*)d_out, nullptr, (const float4*)d_in[14],
                            (const float*)d_in[15]);
}

// round 4
// speedup vs baseline: 1.3272x; 1.3272x over previous
#include <cuda_runtime.h>

#define NN 100000
#define NE 3200000

typedef unsigned long long ull;

// ---------------- device scratch ----------------
__device__ int2   g_edges[NE];      // (src, norm-as-float-bits), CSR by dst
__device__ int    g_src[NE];
__device__ int    g_dst[NE];
__device__ int    g_cnt[NN];
__device__ int    g_rowptr[NN + 1];
__device__ int    g_cursor[NN];
__device__ int    g_bsum[128];
__device__ int    g_bsumEx[128];
__device__ float  g_dinv[NN];
__device__ float4 g_bufA[NN * 4];   // xw  -> (reused) H
__device__ float4 g_bufC[NN * 4];   // xw2
__device__ float4 g_x1[NN * 4];
__device__ float4 g_x2[NN * 4];

// ---------------- helpers ----------------
__device__ __forceinline__ float sigm_f(float x) {
    return __fdividef(1.0f, 1.0f + __expf(-x));
}
__device__ __forceinline__ float tanh_f(float x) {
    float e = __expf(2.0f * x);
    return 1.0f - __fdividef(2.0f, e + 1.0f);
}
__device__ __forceinline__ ull pack2(float a, float b) {
    ull r;
    asm("mov.b64 %0, {%1, %2};" : "=l"(r) : "f"(a), "f"(b));
    return r;
}
__device__ __forceinline__ ull fma2(ull a, ull b, ull c) {
    ull d;
    asm("fma.rn.f32x2 %0, %1, %2, %3;" : "=l"(d) : "l"(a), "l"(b), "l"(c));
    return d;
}
__device__ __forceinline__ void unpack2(ull v, float& a, float& b) {
    asm("mov.b64 {%0, %1}, %2;" : "=f"(a), "=f"(b) : "l"(v));
}
#define FMA2W(acc, w, xv) (acc) = fma2(pack2((w), (w)), (xv), (acc))

// ---------------- graph preprocessing ----------------
__global__ void k_zero() {
    int i = blockIdx.x * blockDim.x + threadIdx.x;
    if (i < NN) g_cnt[i] = 0;
}

__global__ void k_count(const int* __restrict__ ei, int is64) {
    int e = blockIdx.x * blockDim.x + threadIdx.x;
    if (e >= NE) return;
    int s, d;
    if (is64) {
        s = ei[2 * e];
        d = ei[2 * (NE + e)];
    } else {
        s = ei[e];
        d = ei[NE + e];
    }
    g_src[e] = s; g_dst[e] = d;
    atomicAdd(&g_cnt[d], 1);
}

__global__ void k_dinv() {
    int i = blockIdx.x * blockDim.x + threadIdx.x;
    if (i < NN) g_dinv[i] = rsqrtf((float)g_cnt[i] + 1.0f);
}

__global__ void k_scanA() {
    __shared__ int sh[1024];
    int i = blockIdx.x * 1024 + threadIdx.x;
    int v = (i < NN) ? g_cnt[i] : 0;
    sh[threadIdx.x] = v;
    __syncthreads();
    #pragma unroll
    for (int off = 1; off < 1024; off <<= 1) {
        int t = (threadIdx.x >= off) ? sh[threadIdx.x - off] : 0;
        __syncthreads();
        sh[threadIdx.x] += t;
        __syncthreads();
    }
    if (i < NN) g_rowptr[i] = sh[threadIdx.x] - v;
    if (threadIdx.x == 1023) g_bsum[blockIdx.x] = sh[1023];
}

__global__ void k_scanB(int nb) {
    __shared__ int sh[128];
    int t = threadIdx.x;
    int v = (t < nb) ? g_bsum[t] : 0;
    sh[t] = v;
    __syncthreads();
    #pragma unroll
    for (int off = 1; off < 128; off <<= 1) {
        int tv = (t >= off) ? sh[t - off] : 0;
        __syncthreads();
        sh[t] += tv;
        __syncthreads();
    }
    g_bsumEx[t] = sh[t] - v;
}

__global__ void k_scanC() {
    int i = blockIdx.x * blockDim.x + threadIdx.x;
    if (i < NN) {
        int r = g_rowptr[i] + g_bsumEx[i >> 10];
        g_rowptr[i] = r;
        g_cursor[i] = r;
    }
    if (i == 0) g_rowptr[NN] = NE;
}

__global__ void k_scatter() {
    int e = blockIdx.x * blockDim.x + threadIdx.x;
    if (e >= NE) return;
    int s = g_src[e], d = g_dst[e];
    int p = atomicAdd(&g_cursor[d], 1);
    g_edges[p] = make_int2(s, __float_as_int(g_dinv[s] * g_dinv[d]));
}

// ---------------- GEMM1: xw = x[100000,512] @ W1[512,16] (f32x2 packed) --------
__global__ void __launch_bounds__(256) k_gemm1(const float4* __restrict__ x4,
                                               const float* __restrict__ w) {
    __shared__ float xs[256][33];
    __shared__ ulonglong2 sw[128];   // 32 rows x 16 floats as 4 ull2/row
    int tid = threadIdx.x;
    int row = blockIdx.x * 256 + tid;
    ull acc2[8];
    #pragma unroll
    for (int p = 0; p < 8; p++) acc2[p] = 0ULL;

    const ulonglong2* w16 = (const ulonglong2*)w;

    for (int kc = 0; kc < 16; kc++) {
        #pragma unroll
        for (int j = 0; j < 8; j++) {
            int idx = j * 256 + tid;
            int r = idx >> 3, c4 = idx & 7;
            int gr = blockIdx.x * 256 + r;
            float4 v = (gr < NN) ? x4[gr * 128 + kc * 8 + c4]
                                 : make_float4(0.f, 0.f, 0.f, 0.f);
            xs[r][c4 * 4 + 0] = v.x; xs[r][c4 * 4 + 1] = v.y;
            xs[r][c4 * 4 + 2] = v.z; xs[r][c4 * 4 + 3] = v.w;
        }
        if (tid < 128) sw[tid] = w16[kc * 128 + tid];
        __syncthreads();
        #pragma unroll
        for (int k = 0; k < 32; k++) {
            float xv = xs[tid][k];
            ull xd = pack2(xv, xv);
            ulonglong2 w0 = sw[k * 4 + 0], w1 = sw[k * 4 + 1];
            ulonglong2 w2v = sw[k * 4 + 2], w3v = sw[k * 4 + 3];
            acc2[0] = fma2(w0.x,  xd, acc2[0]);
            acc2[1] = fma2(w0.y,  xd, acc2[1]);
            acc2[2] = fma2(w1.x,  xd, acc2[2]);
            acc2[3] = fma2(w1.y,  xd, acc2[3]);
            acc2[4] = fma2(w2v.x, xd, acc2[4]);
            acc2[5] = fma2(w2v.y, xd, acc2[5]);
            acc2[6] = fma2(w3v.x, xd, acc2[6]);
            acc2[7] = fma2(w3v.y, xd, acc2[7]);
        }
        __syncthreads();
    }
    if (row < NN) {
        float o[16];
        #pragma unroll
        for (int p = 0; p < 8; p++) unpack2(acc2[p], o[2 * p], o[2 * p + 1]);
        g_bufA[row * 4 + 0] = make_float4(o[0],  o[1],  o[2],  o[3]);
        g_bufA[row * 4 + 1] = make_float4(o[4],  o[5],  o[6],  o[7]);
        g_bufA[row * 4 + 2] = make_float4(o[8],  o[9],  o[10], o[11]);
        g_bufA[row * 4 + 3] = make_float4(o[12], o[13], o[14], o[15]);
    }
}

// ---------------- GCN aggregation: warp-per-node, 4 lanes per edge --------------
template <int MODE>
__global__ void __launch_bounds__(256) k_agg(float* __restrict__ outp,
                                             const float* __restrict__ bias,
                                             const float4* __restrict__ W4,
                                             const float* __restrict__ Wb) {
    __shared__ float4 sW[160];
    __shared__ float  sx[8][16];
    if (MODE == 0) { if (threadIdx.x < 64)  sW[threadIdx.x] = W4[threadIdx.x]; }
    if (MODE == 2) { if (threadIdx.x < 160) sW[threadIdx.x] = W4[threadIdx.x]; }
    __syncthreads();

    int warp = threadIdx.x >> 5;
    int lane = threadIdx.x & 31;
    int g = lane >> 2, q = lane & 3;
    int n = blockIdx.x * 8 + warp;
    if (n >= NN) return;

    const float4* in4 = (MODE == 1) ? g_bufC : g_bufA;

    float4 acc = make_float4(0.f, 0.f, 0.f, 0.f);
    if (g == 0) {
        float dd = g_dinv[n]; dd *= dd;
        float4 a = in4[n * 4 + q];
        acc.x = dd * a.x; acc.y = dd * a.y; acc.z = dd * a.z; acc.w = dd * a.w;
    }

    int beg = g_rowptr[n], end = g_rowptr[n + 1];
    for (int e = beg + g; e < end; e += 8) {
        int2 ev = g_edges[e];
        float w = __int_as_float(ev.y);
        float4 v = in4[ev.x * 4 + q];
        acc.x += w * v.x; acc.y += w * v.y; acc.z += w * v.z; acc.w += w * v.w;
    }

    #pragma unroll
    for (int off = 4; off < 32; off <<= 1) {
        acc.x += __shfl_xor_sync(0xffffffffu, acc.x, off);
        acc.y += __shfl_xor_sync(0xffffffffu, acc.y, off);
        acc.z += __shfl_xor_sync(0xffffffffu, acc.z, off);
        acc.w += __shfl_xor_sync(0xffffffffu, acc.w, off);
    }

    if (MODE == 0 || MODE == 1) {
        if (g == 0) {
            float4 b = ((const float4*)bias)[q];
            float4 xr;
            xr.x = fmaxf(acc.x + b.x, 0.0f);
            xr.y = fmaxf(acc.y + b.y, 0.0f);
            xr.z = fmaxf(acc.z + b.z, 0.0f);
            xr.w = fmaxf(acc.w + b.w, 0.0f);
            float4* ox = (MODE == 0) ? (g_x1 + n * 4) : (g_x2 + n * 4);
            ox[q] = xr;
            if (MODE == 0) {
                sx[warp][q * 4 + 0] = xr.x; sx[warp][q * 4 + 1] = xr.y;
                sx[warp][q * 4 + 2] = xr.z; sx[warp][q * 4 + 3] = xr.w;
            }
        }
        if (MODE == 0) {
            __syncwarp();
            if (g == 0) {
                float y[4] = {0.f, 0.f, 0.f, 0.f};
                #pragma unroll
                for (int k = 0; k < 16; k++) {
                    float xv = sx[warp][k];
                    float4 w = sW[k * 4 + q];
                    y[0] += xv * w.x; y[1] += xv * w.y;
                    y[2] += xv * w.z; y[3] += xv * w.w;
                }
                g_bufC[n * 4 + q] = make_float4(y[0], y[1], y[2], y[3]);
            }
        }
    } else {  // MODE 2
        if (g == 0) {
            sx[warp][q * 4 + 0] = acc.x; sx[warp][q * 4 + 1] = acc.y;
            sx[warp][q * 4 + 2] = acc.z; sx[warp][q * 4 + 3] = acc.w;
        }
        __syncwarp();
        const float* sWf = (const float*)sW;
        float v0 = __ldg(&Wb[lane]);
        float v1 = (lane < 8) ? __ldg(&Wb[32 + lane]) : -1e30f;
        #pragma unroll
        for (int k = 0; k < 16; k++) {
            float a = sx[warp][k];
            v0 += a * sWf[k * 40 + lane];
            if (lane < 8) v1 += a * sWf[k * 40 + 32 + lane];
        }
        float m = fmaxf(v0, v1);
        #pragma unroll
        for (int off = 1; off < 32; off <<= 1)
            m = fmaxf(m, __shfl_xor_sync(0xffffffffu, m, off));
        float s = __expf(v0 - m) + ((lane < 8) ? __expf(v1 - m) : 0.0f);
        #pragma unroll
        for (int off = 1; off < 32; off <<= 1)
            s += __shfl_xor_sync(0xffffffffu, s, off);
        float lse = m + __logf(s);
        outp[n * 40 + lane] = v0 - lse;
        if (lane < 8) outp[n * 40 + 32 + lane] = v1 - lse;
    }
}

// ---------------- JK bidirectional LSTM: node-pair f32x2 SIMD -------------------
// Each thread processes TWO nodes packed into f32x2 lanes (low=node0, high=node1).
// j-loops stay ROLLED (small code, no I$ thrash); h/c round-trip through shared
// (per-thread columns, conflict-free); w_hh shared region overlaid fwd->bwd.
#define LS_SIHF 0        // float4[512]   8KB  w_ih_f
#define LS_SIHB 8192     // float4[512]   8KB  w_ih_b
#define LS_SHH  16384    // float4[1024] 16KB  w_hh (fwd, then bwd)
#define LS_BF   32768    // float[128]
#define LS_BB   33280    // float[128]
#define LS_AW   33792    // float[64]
#define LS_H    34048    // ull[32*128]  32KB
#define LS_C    66816    // ull[32*128]  32KB
#define SMEM_LSTM 99584

// zero-state cell: gates i,g,o; writes packed h,c to shared; accumulates score
__device__ __forceinline__ void cell0p(const ull* __restrict__ xp,
                                       ull* __restrict__ hsh, ull* __restrict__ csh,
                                       const float4* __restrict__ sih,
                                       const float* __restrict__ sb,
                                       const float* __restrict__ sw, ull& sacc) {
    #pragma unroll 1
    for (int j = 0; j < 32; j++) {
        float bi = sb[j], bg = sb[64 + j], bo = sb[96 + j];
        ull ai = pack2(bi, bi), ag = pack2(bg, bg), ao = pack2(bo, bo);
        #pragma unroll
        for (int q = 0; q < 4; q++) {
            float4 wi = sih[j * 4 + q];
            FMA2W(ai, wi.x, xp[4 * q + 0]); FMA2W(ai, wi.y, xp[4 * q + 1]);
            FMA2W(ai, wi.z, xp[4 * q + 2]); FMA2W(ai, wi.w, xp[4 * q + 3]);
            float4 wg = sih[(64 + j) * 4 + q];
            FMA2W(ag, wg.x, xp[4 * q + 0]); FMA2W(ag, wg.y, xp[4 * q + 1]);
            FMA2W(ag, wg.z, xp[4 * q + 2]); FMA2W(ag, wg.w, xp[4 * q + 3]);
            float4 wo = sih[(96 + j) * 4 + q];
            FMA2W(ao, wo.x, xp[4 * q + 0]); FMA2W(ao, wo.y, xp[4 * q + 1]);
            FMA2W(ao, wo.z, xp[4 * q + 2]); FMA2W(ao, wo.w, xp[4 * q + 3]);
        }
        float i0, i1, g0, g1, o0, o1;
        unpack2(ai, i0, i1); unpack2(ag, g0, g1); unpack2(ao, o0, o1);
        float c0 = sigm_f(i0) * tanh_f(g0), c1 = sigm_f(i1) * tanh_f(g1);
        float h0 = sigm_f(o0) * tanh_f(c0), h1 = sigm_f(o1) * tanh_f(c1);
        csh[j * 128] = pack2(c0, c1);
        ull hp = pack2(h0, h1);
        hsh[j * 128] = hp;
        float awj = sw[j];
        sacc = fma2(hp, pack2(awj, awj), sacc);
    }
}

// full cell: consumes preloaded h (regs) + c (shared); accumulates score only
__device__ __forceinline__ void cell1p(const ull* __restrict__ xp,
                                       const ull* __restrict__ hreg,
                                       const ull* __restrict__ csh,
                                       const float4* __restrict__ sih,
                                       const float4* __restrict__ shh,
                                       const float* __restrict__ sb,
                                       const float* __restrict__ sw, ull& sacc) {
    #pragma unroll 1
    for (int j = 0; j < 32; j++) {
        float bi = sb[j], bff = sb[32 + j], bg = sb[64 + j], bo = sb[96 + j];
        ull ai = pack2(bi, bi), af = pack2(bff, bff);
        ull ag = pack2(bg, bg), ao = pack2(bo, bo);
        #pragma unroll
        for (int q = 0; q < 4; q++) {
            float4 wi = sih[j * 4 + q];
            FMA2W(ai, wi.x, xp[4 * q + 0]); FMA2W(ai, wi.y, xp[4 * q + 1]);
            FMA2W(ai, wi.z, xp[4 * q + 2]); FMA2W(ai, wi.w, xp[4 * q + 3]);
            float4 wf = sih[(32 + j) * 4 + q];
            FMA2W(af, wf.x, xp[4 * q + 0]); FMA2W(af, wf.y, xp[4 * q + 1]);
            FMA2W(af, wf.z, xp[4 * q + 2]); FMA2W(af, wf.w, xp[4 * q + 3]);
            float4 wg = sih[(64 + j) * 4 + q];
            FMA2W(ag, wg.x, xp[4 * q + 0]); FMA2W(ag, wg.y, xp[4 * q + 1]);
            FMA2W(ag, wg.z, xp[4 * q + 2]); FMA2W(ag, wg.w, xp[4 * q + 3]);
            float4 wo = sih[(96 + j) * 4 + q];
            FMA2W(ao, wo.x, xp[4 * q + 0]); FMA2W(ao, wo.y, xp[4 * q + 1]);
            FMA2W(ao, wo.z, xp[4 * q + 2]); FMA2W(ao, wo.w, xp[4 * q + 3]);
        }
        #pragma unroll
        for (int q = 0; q < 8; q++) {
            float4 wi = shh[j * 8 + q];
            FMA2W(ai, wi.x, hreg[4 * q + 0]); FMA2W(ai, wi.y, hreg[4 * q + 1]);
            FMA2W(ai, wi.z, hreg[4 * q + 2]); FMA2W(ai, wi.w, hreg[4 * q + 3]);
            float4 wf = shh[(32 + j) * 8 + q];
            FMA2W(af, wf.x, hreg[4 * q + 0]); FMA2W(af, wf.y, hreg[4 * q + 1]);
            FMA2W(af, wf.z, hreg[4 * q + 2]); FMA2W(af, wf.w, hreg[4 * q + 3]);
            float4 wg = shh[(64 + j) * 8 + q];
            FMA2W(ag, wg.x, hreg[4 * q + 0]); FMA2W(ag, wg.y, hreg[4 * q + 1]);
            FMA2W(ag, wg.z, hreg[4 * q + 2]); FMA2W(ag, wg.w, hreg[4 * q + 3]);
            float4 wo = shh[(96 + j) * 8 + q];
            FMA2W(ao, wo.x, hreg[4 * q + 0]); FMA2W(ao, wo.y, hreg[4 * q + 1]);
            FMA2W(ao, wo.z, hreg[4 * q + 2]); FMA2W(ao, wo.w, hreg[4 * q + 3]);
        }
        float i0, i1, f0, f1, g0, g1, o0, o1;
        unpack2(ai, i0, i1); unpack2(af, f0, f1);
        unpack2(ag, g0, g1); unpack2(ao, o0, o1);
        float cp0, cp1;
        unpack2(csh[j * 128], cp0, cp1);
        float c0 = sigm_f(f0) * cp0 + sigm_f(i0) * tanh_f(g0);
        float c1 = sigm_f(f1) * cp1 + sigm_f(i1) * tanh_f(g1);
        float h0 = sigm_f(o0) * tanh_f(c0), h1 = sigm_f(o1) * tanh_f(c1);
        float awj = sw[j];
        sacc = fma2(pack2(h0, h1), pack2(awj, awj), sacc);
    }
}

__global__ void __launch_bounds__(128, 2) k_lstm(
    const float4* __restrict__ wihf, const float4* __restrict__ whhf, const float* __restrict__ bf,
    const float4* __restrict__ wihb, const float4* __restrict__ whhb, const float* __restrict__ bb,
    const float* __restrict__ aw, const float* __restrict__ ab) {
    extern __shared__ char sm[];
    float4* sihf = (float4*)(sm + LS_SIHF);
    float4* sihb = (float4*)(sm + LS_SIHB);
    float4* shh  = (float4*)(sm + LS_SHH);
    float*  sbf  = (float*)(sm + LS_BF);
    float*  sbb  = (float*)(sm + LS_BB);
    float*  saw  = (float*)(sm + LS_AW);
    int tid = threadIdx.x;
    ull* hsh = (ull*)(sm + LS_H) + tid;
    ull* csh = (ull*)(sm + LS_C) + tid;

    for (int i = tid; i < 512; i += 128) { sihf[i] = wihf[i]; sihb[i] = wihb[i]; }
    for (int i = tid; i < 1024; i += 128) shh[i] = whhf[i];
    if (tid < 64) {
        sbf[tid] = bf[tid]; sbf[64 + tid] = bf[64 + tid];
        sbb[tid] = bb[tid]; sbb[64 + tid] = bb[64 + tid];
        saw[tid] = aw[tid];
    }
    __syncthreads();

    int n0 = blockIdx.x * 256 + tid;
    int n1 = n0 + 128;
    bool v0 = n0 < NN, v1 = n1 < NN;
    int m0 = v0 ? n0 : 0, m1 = v1 ? n1 : 0;

    ull xpa[16], xpb[16];
    {
        #pragma unroll
        for (int q = 0; q < 4; q++) {
            float4 a = g_x1[m0 * 4 + q], b = g_x1[m1 * 4 + q];
            xpa[4 * q + 0] = pack2(a.x, b.x); xpa[4 * q + 1] = pack2(a.y, b.y);
            xpa[4 * q + 2] = pack2(a.z, b.z); xpa[4 * q + 3] = pack2(a.w, b.w);
            float4 c = g_x2[m0 * 4 + q], d = g_x2[m1 * 4 + q];
            xpb[4 * q + 0] = pack2(c.x, d.x); xpb[4 * q + 1] = pack2(c.y, d.y);
            xpb[4 * q + 2] = pack2(c.z, d.z); xpb[4 * q + 3] = pack2(c.w, d.w);
        }
    }

    ull s0 = 0ULL, s1 = 0ULL;
    ull hreg[32];

    // forward: cell t=0 on x1, then t=1 on x2
    cell0p(xpa, hsh, csh, sihf, sbf, saw, s0);
    #pragma unroll
    for (int k = 0; k < 32; k++) hreg[k] = hsh[k * 128];
    cell1p(xpb, hreg, csh, sihf, shh, sbf, saw, s1);

    // overlay w_hh_b into shh
    __syncthreads();
    for (int i = tid; i < 1024; i += 128) shh[i] = whhb[i];
    __syncthreads();

    // backward: cell t=1 on x2, then t=0 on x1
    cell0p(xpb, hsh, csh, sihb, sbb, saw + 32, s1);
    #pragma unroll
    for (int k = 0; k < 32; k++) hreg[k] = hsh[k * 128];
    cell1p(xpa, hreg, csh, sihb, shh, sbb, saw + 32, s0);

    float abv = __ldg(ab);
    float s00, s01, s10, s11;
    unpack2(s0, s00, s01); unpack2(s1, s10, s11);
    s00 += abv; s01 += abv; s10 += abv; s11 += abv;

    float mA = fmaxf(s00, s10);
    float eA0 = __expf(s00 - mA), eA1 = __expf(s10 - mA);
    float invA = __fdividef(1.0f, eA0 + eA1);
    float A0 = eA0 * invA, B0 = eA1 * invA;

    float mB = fmaxf(s01, s11);
    float eB0 = __expf(s01 - mB), eB1 = __expf(s11 - mB);
    float invB = __fdividef(1.0f, eB0 + eB1);
    float A1 = eB0 * invB, B1 = eB1 * invB;

    float fa[16], fb[16], ga[16], gb[16];
    #pragma unroll
    for (int k = 0; k < 16; k++) {
        float lo, hi;
        unpack2(xpa[k], lo, hi); fa[k] = lo; ga[k] = hi;
        unpack2(xpb[k], lo, hi); fb[k] = lo; gb[k] = hi;
    }
    if (v0) {
        #pragma unroll
        for (int q = 0; q < 4; q++) {
            g_bufA[n0 * 4 + q] = make_float4(
                A0 * fa[4 * q + 0] + B0 * fb[4 * q + 0],
                A0 * fa[4 * q + 1] + B0 * fb[4 * q + 1],
                A0 * fa[4 * q + 2] + B0 * fb[4 * q + 2],
                A0 * fa[4 * q + 3] + B0 * fb[4 * q + 3]);
        }
    }
    if (v1) {
        #pragma unroll
        for (int q = 0; q < 4; q++) {
            g_bufA[n1 * 4 + q] = make_float4(
                A1 * ga[4 * q + 0] + B1 * gb[4 * q + 0],
                A1 * ga[4 * q + 1] + B1 * gb[4 * q + 1],
                A1 * ga[4 * q + 2] + B1 * gb[4 * q + 2],
                A1 * ga[4 * q + 3] + B1 * gb[4 * q + 3]);
        }
    }
}

// ---------------- launch ----------------
extern "C" void kernel_launch(void* const* d_in, const int* in_sizes, int n_in,
                              void* d_out, int out_size) {
    int is64 = (in_sizes[1] >= 4 * NE) ? 1 : 0;

    const int NB_N  = (NN + 255) / 256;
    const int NB_E  = (NE + 255) / 256;
    const int NB_SC = (NN + 1023) / 1024;
    const int NB_W  = (NN + 7) / 8;
    const int NB_L  = (NN + 255) / 256;   // 256 nodes per LSTM block (128 thr x 2)

    cudaFuncSetAttribute(k_lstm, cudaFuncAttributeMaxDynamicSharedMemorySize, SMEM_LSTM);

    k_zero<<<NB_N, 256>>>();
    k_count<<<NB_E, 256>>>((const int*)d_in[1], is64);
    k_dinv<<<NB_N, 256>>>();
    k_scanA<<<NB_SC, 1024>>>();
    k_scanB<<<1, 128>>>(NB_SC);
    k_scanC<<<NB_N, 256>>>();
    k_scatter<<<NB_E, 256>>>();

    k_gemm1<<<NB_N, 256>>>((const float4*)d_in[0], (const float*)d_in[2]);

    k_agg<0><<<NB_W, 256>>>(nullptr, (const float*)d_in[3], (const float4*)d_in[4], nullptr);
    k_agg<1><<<NB_W, 256>>>(nullptr, (const float*)d_in[5], nullptr, nullptr);

    k_lstm<<<NB_L, 128, SMEM_LSTM>>>(
        (const float4*)d_in[6], (const float4*)d_in[7], (const float*)d_in[8],
        (const float4*)d_in[9], (const float4*)d_in[10], (const float*)d_in[11],
        (const float*)d_in[12], (const float*)d_in[13]);

    k_agg<2><<<NB_W, 256>>>((float*)d_out, nullptr, (const float4*)d_in[14],
                            (const float*)d_in[15]);
}